// round 16
// baseline (speedup 1.0000x reference)
#include <cuda_runtime.h>

#define NTOK 512
#define DSTATE 192
#define HID 512
#define EMB 1024
#define NEMB 32
#define KC 256   // K rows per block (HID / 2 k-halves)
#define CHT 24   // tokens per chunk (P <= 12 pairs)
#define HSS 28   // hs row stride (floats): 112 B rows, 16B-aligned
#define XSS 28   // xs row stride (floats)

struct Params {
    const float* W1[4];
    const float* b1[4];
    const float* W2[4];
    const float* b2[4];
    const float* te[4];
};

__device__ __forceinline__ void fma2(unsigned long long& acc,
                                     unsigned long long h2,
                                     unsigned long long w2) {
    asm("fma.rn.f32x2 %0, %1, %2, %0;" : "+l"(acc) : "l"(h2), "l"(w2));
}
__device__ __forceinline__ unsigned long long splat2(float v) {
    unsigned long long r;
    asm("mov.b64 %0, {%1,%1};" : "=l"(r) : "r"(__float_as_uint(v)));
    return r;
}

#define WD 8  // W2 prefetch group size (LDG.64 each -> 16 lines/warp)

template <int P>
__device__ __forceinline__ void consume(const float2* w, const float* hs, int g,
                                        unsigned long long* a0, unsigned long long* a1) {
    #pragma unroll
    for (int j = 0; j < WD; j++) {
        unsigned long long w0 = splat2(w[j].x);
        unsigned long long w1 = splat2(w[j].y);
        const float* hrow = hs + (g + j) * HSS;
        #pragma unroll
        for (int p2 = 0; p2 < P / 2; p2++) {
            ulonglong2 hv = *(const ulonglong2*)(hrow + 4 * p2); // LDS.128 bcast
            fma2(a0[2 * p2],     hv.x, w0);
            fma2(a0[2 * p2 + 1], hv.y, w0);
            fma2(a1[2 * p2],     hv.x, w1);
            fma2(a1[2 * p2 + 1], hv.y, w1);
        }
    }
}

// One chunk: prologue computes this block's h-half straight into smem, then
// the proven W2 double-buffered mainloop, then the atomic epilogue.
template <int P, int L, int OFF>  // P even 2..12 token pairs
__device__ __forceinline__ void run_chunk(
    float* hs, float* xs, const int* s_tok, int n,
    const float* __restrict__ state,
    const float* __restrict__ W1ec, float2 b1v,
    const float* __restrict__ W2ec,
    float2 init, int cb, int rem, int tid, int c0, int m,
    float* __restrict__ out)
{
    // ---- gather x (2P tokens, clamp pad; pad rows discarded by rem) ----
    __syncthreads();
    #pragma unroll 1
    for (int idx = tid; idx < 2 * P * L; idx += 128) {
        int tk = idx / L, l = idx - tk * L;
        int tok = s_tok[min(cb + tk, n - 1)];
        xs[l * XSS + tk] = state[tok * DSTATE + OFF + l];
    }
    __syncthreads();

    {   // ---- h = relu(x . W1half + b1) for hs rows {2*tid, 2*tid+1} ----
        unsigned long long hA[P], hB[P];
        unsigned long long bA = splat2(b1v.x), bB = splat2(b1v.y);
        #pragma unroll
        for (int p = 0; p < P; p++) { hA[p] = bA; hB[p] = bB; }

        #pragma unroll 1
        for (int l0 = 0; l0 < L; l0 += 8) {
            float2 w[8];
            #pragma unroll
            for (int u = 0; u < 8; u++)
                w[u] = *(const float2*)(W1ec + (size_t)(l0 + u) * HID);
            #pragma unroll
            for (int u = 0; u < 8; u++) {
                unsigned long long w0 = splat2(w[u].x);
                unsigned long long w1 = splat2(w[u].y);
                const float* xrow = xs + (l0 + u) * XSS;
                #pragma unroll
                for (int p2 = 0; p2 < P / 2; p2++) {
                    ulonglong2 xv = *(const ulonglong2*)(xrow + 4 * p2);
                    fma2(hA[2 * p2],     xv.x, w0);
                    fma2(hA[2 * p2 + 1], xv.y, w0);
                    fma2(hB[2 * p2],     xv.x, w1);
                    fma2(hB[2 * p2 + 1], xv.y, w1);
                }
            }
        }
        float* rowA = hs + (2 * tid) * HSS;
        float* rowB = hs + (2 * tid + 1) * HSS;
        #pragma unroll
        for (int p = 0; p < P; p++) {
            float2 a = *(float2*)&hA[p];
            float2 b = *(float2*)&hB[p];
            a.x = fmaxf(a.x, 0.f); a.y = fmaxf(a.y, 0.f);
            b.x = fmaxf(b.x, 0.f); b.y = fmaxf(b.y, 0.f);
            *(float2*)&rowA[2 * p] = a;
            *(float2*)&rowB[2 * p] = b;
        }
    }
    __syncthreads();

    // ---- mainloop: W2 half stream, double-buffered (R14 proven) ----
    unsigned long long a0[P], a1[P];
    unsigned long long i0 = splat2(init.x), i1 = splat2(init.y);
    #pragma unroll
    for (int p = 0; p < P; p++) { a0[p] = i0; a1[p] = i1; }

    float2 wA[WD], wB[WD];
    #pragma unroll
    for (int j = 0; j < WD; j++)
        wA[j] = __ldcs((const float2*)(W2ec + (size_t)j * EMB));

    #pragma unroll 1
    for (int g = 0; g < KC - 2 * WD; g += 2 * WD) {
        #pragma unroll
        for (int j = 0; j < WD; j++)
            wB[j] = __ldcs((const float2*)(W2ec + (size_t)(g + WD + j) * EMB));
        consume<P>(wA, hs, g, a0, a1);
        #pragma unroll
        for (int j = 0; j < WD; j++)
            wA[j] = __ldcs((const float2*)(W2ec + (size_t)(g + 2 * WD + j) * EMB));
        consume<P>(wB, hs, g + WD, a0, a1);
    }
    #pragma unroll
    for (int j = 0; j < WD; j++)
        wB[j] = __ldcs((const float2*)(W2ec + (size_t)(KC - WD + j) * EMB));
    consume<P>(wA, hs, KC - 2 * WD, a0, a1);
    consume<P>(wB, hs, KC - WD, a0, a1);

    // ---- atomic epilogue: out memset to 0; two commutative adds/element ----
    #pragma unroll
    for (int p = 0; p < P; p++) {
        float2 vA = *(float2*)&a0[p];
        float2 vB = *(float2*)&a1[p];
        int t0 = 2 * p;
        if (t0 < rem) {
            int tok = s_tok[cb + t0];
            float* dst = &out[((size_t)tok * 4 + m) * EMB + c0];
            atomicAdd(dst,     vA.x);
            atomicAdd(dst + 1, vB.x);
        }
        if (t0 + 1 < rem) {
            int tok = s_tok[cb + t0 + 1];
            float* dst = &out[((size_t)tok * 4 + m) * EMB + c0];
            atomicAdd(dst,     vA.y);
            atomicAdd(dst + 1, vB.y);
        }
    }
}

template <int L, int OFF>
__device__ __forceinline__ void body(
    const Params& p, const float* __restrict__ state, float* __restrict__ out,
    int m, int e, int kh, int tile, int n,
    float* hs, float* xs, const int* s_tok)
{
    int tid = threadIdx.x;
    int c0 = tile * 256 + tid * 2;
    int j0 = kh * KC + 2 * tid;  // this thread's hidden cols (= hs rows)
    const float* W2ec = p.W2[m] + (size_t)e * HID * EMB + (size_t)kh * KC * EMB + c0;
    const float* W1ec = p.W1[m] + (size_t)e * L * HID + j0;
    float2 b1v = *(const float2*)&p.b1[m][e * HID + j0];
    float2 init = (kh == 0)
        ? make_float2(p.b2[m][e * EMB + c0]     + p.te[m][c0],
                      p.b2[m][e * EMB + c0 + 1] + p.te[m][c0 + 1])
        : make_float2(0.f, 0.f);

    for (int cb = 0; cb < n; cb += CHT) {
        int rem = min(n - cb, CHT);
        int pairsEven = ((rem + 3) >> 2) << 1; // even ceil(rem/2)
        switch (pairsEven) {
#define CASE(PP) case PP: run_chunk<PP, L, OFF>(hs, xs, s_tok, n, state, W1ec, b1v, \
                          W2ec, init, cb, rem, tid, c0, m, out); break;
            CASE(2) CASE(4) CASE(6) CASE(8) CASE(10) CASE(12)
#undef CASE
        }
    }
}

__global__ void __launch_bounds__(128, 4) k_fused(Params p,
                                                  const float* __restrict__ state,
                                                  const int* __restrict__ ids_raw,
                                                  float* __restrict__ out) {
    __shared__ __align__(16) float hs[KC * HSS];   // 28672 B
    __shared__ __align__(16) float xs[64 * XSS];   //  7168 B
    __shared__ int s_tok[NTOK];                    //  2048 B
    __shared__ int s_segcnt[16], s_segoff[17];
    __shared__ int s_i64;

    int tid  = threadIdx.x;            // 128
    int warp = tid >> 5, lane = tid & 31;
    int tile = blockIdx.x & 3;
    int kh   = blockIdx.x >> 2;
    int m    = blockIdx.y;
    int e    = blockIdx.z;

    // ---- per-block ballot-collect of tokens with id == e (token order) ----
    if (tid == 0) s_i64 = 1;
    __syncthreads();
    // int64 ids (<32) have zero high words at odd int32 indices; indices
    // 2t+1 for t<256 stay within the 512-word buffer for int32 inputs too.
    if (ids_raw[2 * tid + 1] != 0) s_i64 = 0;             // t = tid   (<128)
    if (ids_raw[2 * (tid + 128) + 1] != 0) s_i64 = 0;     // t = tid+128
    __syncthreads();
    int i64 = s_i64;

    bool mine[4];
    int  rk[4];
    #pragma unroll
    for (int r = 0; r < 4; r++) {
        int t = r * 128 + tid;
        int c = i64 ? ids_raw[2 * t] : ids_raw[t];
        bool is = (c == e);
        unsigned bal = __ballot_sync(0xffffffffu, is);
        mine[r] = is;
        rk[r] = __popc(bal & ((1u << lane) - 1u));
        if (lane == 0) s_segcnt[r * 4 + warp] = __popc(bal);
    }
    __syncthreads();
    if (tid == 0) {
        int s = 0;
        #pragma unroll
        for (int i = 0; i < 16; i++) { s_segoff[i] = s; s += s_segcnt[i]; }
        s_segoff[16] = s;
    }
    __syncthreads();
    int n = s_segoff[16];
    if (n == 0) return;
    #pragma unroll
    for (int r = 0; r < 4; r++)
        if (mine[r]) s_tok[s_segoff[r * 4 + warp] + rk[r]] = r * 128 + tid;
    __syncthreads();

    switch (m) {
        case 0: body<64, 0  >(p, state, out, 0, e, kh, tile, n, hs, xs, s_tok); break;
        case 1: body<64, 64 >(p, state, out, 1, e, kh, tile, n, hs, xs, s_tok); break;
        case 2: body<32, 128>(p, state, out, 2, e, kh, tile, n, hs, xs, s_tok); break;
        case 3: body<32, 160>(p, state, out, 3, e, kh, tile, n, hs, xs, s_tok); break;
    }
}

// ---------------------------------------------------------------------------
extern "C" void kernel_launch(void* const* d_in, const int* in_sizes, int n_in,
                              void* d_out, int out_size) {
    const float* state = (const float*)d_in[0];
    const int*   ids   = (const int*)d_in[1];

    Params P;
    int base = 2;
    for (int m = 0; m < 4; m++) {
        P.W1[m] = (const float*)d_in[base + 0];
        P.b1[m] = (const float*)d_in[base + 1];
        P.W2[m] = (const float*)d_in[base + 2];
        P.b2[m] = (const float*)d_in[base + 3];
        P.te[m] = (const float*)d_in[base + 4];
        base += 5;
    }
    float* out = (float*)d_out;

    // zero-init output (graph-capturable memset node; atomics accumulate)
    cudaMemsetAsync(out, 0, (size_t)out_size * sizeof(float));

    k_fused<<<dim3(8, 4, 32), 128>>>(P, state, ids, out);
}

// round 17
// speedup vs baseline: 1.0084x; 1.0084x over previous
#include <cuda_runtime.h>

#define NTOK 512
#define DSTATE 192
#define HID 512
#define EMB 1024
#define NEMB 32
#define KC 256   // K rows per stage2 block (HID / 2 k-halves)
#define CHT 24   // tokens per stage2 chunk (P <= 12 pairs)
#define HSS 28   // smem row stride (floats): 112 B rows, 16B-aligned

// scratch (allocs forbidden -> device globals)
__device__ int g_start[NEMB + 1];
__device__ int g_tokens[NTOK];
__device__ float g_H[NTOK * 4 * HID];  // [slot][m][HID]

struct Params {
    const float* W1[4];
    const float* b1[4];
    const float* W2[4];
    const float* b2[4];
    const float* te[4];
};

// ---------------------------------------------------------------------------
// Stage 1: grid (jh 2, m 4, e 32) = 256 blocks x 256 threads.
// Grouping re-derived per block (deterministic match/histogram, 2 ids/thread);
// block (0,0,0) publishes. Inner MLP body identical to the proven R9 version.
// ---------------------------------------------------------------------------
template <int L, int OFF>
__device__ __forceinline__ void mlp1(const float* __restrict__ state,
                                     const float* __restrict__ W1,
                                     float b, int m, int j, int s0, int n,
                                     const int* __restrict__ s_tokens,
                                     float* __restrict__ xs) {
    int tid = threadIdx.x; // 256
    for (int cb = 0; cb < n; cb += 16) {
        int rem = min(n - cb, 16);
        __syncthreads();
        for (int idx = tid; idx < 16 * L; idx += 256) {
            int tk = idx / L, l = idx % L;
            float v = 0.f;
            if (tk < rem) {
                int tok = s_tokens[s0 + cb + tk];
                v = state[tok * DSTATE + OFF + l];
            }
            xs[tk * L + l] = v;
        }
        __syncthreads();

        float acc[16];
        #pragma unroll
        for (int t = 0; t < 16; t++) acc[t] = b;

        #pragma unroll 1
        for (int l0 = 0; l0 < L; l0 += 8) {
            float w[8];
            #pragma unroll
            for (int u = 0; u < 8; u++)
                w[u] = W1[(l0 + u) * HID + j];
            #pragma unroll
            for (int u = 0; u < 8; u++) {
                #pragma unroll
                for (int t = 0; t < 16; t++)
                    acc[t] = fmaf(xs[t * L + l0 + u], w[u], acc[t]);
            }
        }

        #pragma unroll
        for (int t = 0; t < 16; t++) {
            if (t < rem)
                g_H[((size_t)(s0 + cb + t) * 4 + m) * HID + j] = fmaxf(acc[t], 0.f);
        }
        __syncthreads();
    }
}

__global__ void __launch_bounds__(256) k_stage1(const float* __restrict__ state,
                                                const int* __restrict__ ids_raw,
                                                Params p) {
    __shared__ int s_start[NEMB + 1];
    __shared__ int s_tokens[NTOK];
    __shared__ int s_wcnt[16 * NEMB];
    __shared__ int s_woff[16 * NEMB];
    __shared__ int s_i64;
    __shared__ float xs[16 * 64];

    int tid  = threadIdx.x; // 256
    int warp = tid >> 5, lane = tid & 31;

    s_wcnt[tid] = 0;
    s_wcnt[tid + 256] = 0;
    if (tid == 0) s_i64 = 1;
    __syncthreads();
    // int64 ids (<32) have zero high words at odd int32 indices.
    if (ids_raw[2 * tid + 1] != 0) s_i64 = 0;
    __syncthreads();
    int tA = tid, tB = tid + 256;
    int cA = s_i64 ? ids_raw[2 * tA] : ids_raw[tA];
    int cB = s_i64 ? ids_raw[2 * tB] : ids_raw[tB];

    unsigned sameA = __match_any_sync(0xffffffffu, cA);
    int rankA = __popc(sameA & ((1u << lane) - 1u));
    if (rankA == 0) s_wcnt[warp * NEMB + cA] = __popc(sameA);
    unsigned sameB = __match_any_sync(0xffffffffu, cB);
    int rankB = __popc(sameB & ((1u << lane) - 1u));
    if (rankB == 0) s_wcnt[(8 + warp) * NEMB + cB] = __popc(sameB);
    __syncthreads();

    if (tid < NEMB) {
        int sum = 0;
        #pragma unroll
        for (int w = 0; w < 16; w++) {
            int c = s_wcnt[w * NEMB + tid];
            s_woff[w * NEMB + tid] = sum;
            sum += c;
        }
        s_wcnt[tid] = sum; // total per id
    }
    __syncthreads();
    if (tid <= NEMB) {
        int s = 0;
        for (int jj = 0; jj < tid && jj < NEMB; jj++) s += s_wcnt[jj];
        s_start[tid] = s;
    }
    __syncthreads();

    s_tokens[s_start[cA] + s_woff[warp * NEMB + cA] + rankA] = tA;
    s_tokens[s_start[cB] + s_woff[(8 + warp) * NEMB + cB] + rankB] = tB;
    __syncthreads();

    if (blockIdx.x == 0 && blockIdx.y == 0 && blockIdx.z == 0) {
        if (tid <= NEMB) g_start[tid] = s_start[tid];
        g_tokens[tA] = s_tokens[tA];
        g_tokens[tB] = s_tokens[tB];
    }

    // ---- per-block MLP: (jh, m, e) ----
    int jh = blockIdx.x;       // 0..1
    int m  = blockIdx.y;       // 0..3
    int e  = blockIdx.z;       // 0..31
    int j  = jh * 256 + tid;

    int s0 = s_start[e];
    int n  = s_start[e + 1] - s0;
    if (n == 0) return;

    float b;
    switch (m) {
        case 0: b = p.b1[0][e * HID + j];
                mlp1<64, 0  >(state, p.W1[0] + (size_t)e * 64 * HID, b, 0, j, s0, n, s_tokens, xs); break;
        case 1: b = p.b1[1][e * HID + j];
                mlp1<64, 64 >(state, p.W1[1] + (size_t)e * 64 * HID, b, 1, j, s0, n, s_tokens, xs); break;
        case 2: b = p.b1[2][e * HID + j];
                mlp1<32, 128>(state, p.W1[2] + (size_t)e * 32 * HID, b, 2, j, s0, n, s_tokens, xs); break;
        case 3: b = p.b1[3][e * HID + j];
                mlp1<32, 160>(state, p.W1[3] + (size_t)e * 32 * HID, b, 3, j, s0, n, s_tokens, xs); break;
    }
}

// ---------------------------------------------------------------------------
// Stage 2 (K-split, atomic epilogue): byte-identical to the R14 champion.
// ---------------------------------------------------------------------------
__device__ __forceinline__ void fma2(unsigned long long& acc,
                                     unsigned long long h2,
                                     unsigned long long w2) {
    asm("fma.rn.f32x2 %0, %1, %2, %0;" : "+l"(acc) : "l"(h2), "l"(w2));
}
__device__ __forceinline__ unsigned long long splat2(float v) {
    unsigned long long r;
    asm("mov.b64 %0, {%1,%1};" : "=l"(r) : "r"(__float_as_uint(v)));
    return r;
}

#define WD 8  // W2 prefetch group size (LDG.64 each -> 16 lines/warp)

template <int P>
__device__ __forceinline__ void consume(const float2* w, const float* hs, int g,
                                        unsigned long long* a0, unsigned long long* a1) {
    #pragma unroll
    for (int j = 0; j < WD; j++) {
        unsigned long long w0 = splat2(w[j].x);
        unsigned long long w1 = splat2(w[j].y);
        const float* hrow = hs + (g + j) * HSS;
        #pragma unroll
        for (int p2 = 0; p2 < P / 2; p2++) {
            ulonglong2 hv = *(const ulonglong2*)(hrow + 4 * p2); // LDS.128 bcast
            fma2(a0[2 * p2],     hv.x, w0);
            fma2(a0[2 * p2 + 1], hv.y, w0);
            fma2(a1[2 * p2],     hv.x, w1);
            fma2(a1[2 * p2 + 1], hv.y, w1);
        }
    }
}

template <int P>  // P even, 2..12: token pairs in flight
__device__ __forceinline__ void run_chunk(
    float* hs, const float* __restrict__ W2ec, const float* __restrict__ Hme,
    float2 init, int s0cb, int rem, int tid, int c0, int m,
    float* __restrict__ out)
{
    unsigned long long a0[P], a1[P];
    unsigned long long i0 = splat2(init.x), i1 = splat2(init.y);
    #pragma unroll
    for (int p = 0; p < P; p++) { a0[p] = i0; a1[p] = i1; }

    __syncthreads();
    // stage h transposed: hs[kk*HSS + tk], tk in [0, 2P); Hme pre-offset kh*KC
    #pragma unroll
    for (int tk = 0; tk < 2 * P; tk++) {
        int slot = min(s0cb + tk, NTOK - 1); // clamp pad (discarded later)
        const float* src = Hme + (size_t)slot * (4 * HID);
        #pragma unroll
        for (int kk = 0; kk < KC; kk += 128)
            hs[(kk + tid) * HSS + tk] = src[kk + tid];
    }
    __syncthreads();

    float2 wA[WD], wB[WD];
    #pragma unroll
    for (int j = 0; j < WD; j++)
        wA[j] = __ldcs((const float2*)(W2ec + (size_t)j * EMB));

    #pragma unroll 1
    for (int g = 0; g < KC - 2 * WD; g += 2 * WD) {
        #pragma unroll
        for (int j = 0; j < WD; j++)
            wB[j] = __ldcs((const float2*)(W2ec + (size_t)(g + WD + j) * EMB));
        consume<P>(wA, hs, g, a0, a1);
        #pragma unroll
        for (int j = 0; j < WD; j++)
            wA[j] = __ldcs((const float2*)(W2ec + (size_t)(g + 2 * WD + j) * EMB));
        consume<P>(wB, hs, g + WD, a0, a1);
    }
    #pragma unroll
    for (int j = 0; j < WD; j++)
        wB[j] = __ldcs((const float2*)(W2ec + (size_t)(KC - WD + j) * EMB));
    consume<P>(wA, hs, KC - 2 * WD, a0, a1);
    consume<P>(wB, hs, KC - WD, a0, a1);

    // ---- atomic epilogue: out memset to 0; two commutative adds/element ----
    #pragma unroll
    for (int p = 0; p < P; p++) {
        float2 vA = *(float2*)&a0[p]; // col c0:   (tok 2p, tok 2p+1)
        float2 vB = *(float2*)&a1[p]; // col c0+1
        int t0 = 2 * p;
        if (t0 < rem) {
            int tok = g_tokens[s0cb + t0];
            float* dst = &out[((size_t)tok * 4 + m) * EMB + c0];
            atomicAdd(dst,     vA.x);
            atomicAdd(dst + 1, vB.x);
        }
        if (t0 + 1 < rem) {
            int tok = g_tokens[s0cb + t0 + 1];
            float* dst = &out[((size_t)tok * 4 + m) * EMB + c0];
            atomicAdd(dst,     vA.y);
            atomicAdd(dst + 1, vB.y);
        }
    }
}

__global__ void __launch_bounds__(128, 4) k_stage2(Params p, float* __restrict__ out) {
    int bx   = blockIdx.x;     // 0..7 = tile(0..3) | kh<<2
    int tile = bx & 3;
    int kh   = bx >> 2;        // k-half: W2 rows [kh*256, +256)
    int m    = blockIdx.y;     // 0..3
    int e    = blockIdx.z;     // 0..31
    int s0 = g_start[e];
    int n  = g_start[e + 1] - s0;
    if (n == 0) return;

    int tid = threadIdx.x;
    int c0 = tile * 256 + tid * 2;
    const float* __restrict__ W2ec = p.W2[m] + (size_t)e * HID * EMB
                                   + (size_t)kh * KC * EMB + c0;
    const float* __restrict__ Hme  = g_H + m * HID + kh * KC;
    float2 init = (kh == 0)
        ? make_float2(p.b2[m][e * EMB + c0]     + p.te[m][c0],
                      p.b2[m][e * EMB + c0 + 1] + p.te[m][c0 + 1])
        : make_float2(0.f, 0.f);

    __shared__ __align__(16) float hs[KC * HSS];

    for (int cb = 0; cb < n; cb += CHT) {
        int rem = min(n - cb, CHT);
        int pairsEven = ((rem + 3) >> 2) << 1; // even ceil(rem/2)
        int s0cb = s0 + cb;
        switch (pairsEven) {
#define CASE(PP) case PP: run_chunk<PP>(hs, W2ec, Hme, init, s0cb, rem, tid, c0, m, out); break;
            CASE(2) CASE(4) CASE(6) CASE(8) CASE(10) CASE(12)
#undef CASE
        }
    }
}

// ---------------------------------------------------------------------------
extern "C" void kernel_launch(void* const* d_in, const int* in_sizes, int n_in,
                              void* d_out, int out_size) {
    const float* state = (const float*)d_in[0];
    const int*   ids   = (const int*)d_in[1];

    Params P;
    int base = 2;
    for (int m = 0; m < 4; m++) {
        P.W1[m] = (const float*)d_in[base + 0];
        P.b1[m] = (const float*)d_in[base + 1];
        P.W2[m] = (const float*)d_in[base + 2];
        P.b2[m] = (const float*)d_in[base + 3];
        P.te[m] = (const float*)d_in[base + 4];
        base += 5;
    }
    float* out = (float*)d_out;

    // zero-init output (graph-capturable memset node; atomics accumulate)
    cudaMemsetAsync(out, 0, (size_t)out_size * sizeof(float));

    k_stage1<<<dim3(2, 4, 32), 256>>>(state, ids, P);
    k_stage2<<<dim3(8, 4, 32), 128>>>(P, out);
}